// round 15
// baseline (speedup 1.0000x reference)
#include <cuda_runtime.h>

// AggregateJoint: per-row block-diagonal MLP 64 -> (16x16) -> (16x3)
// with leaky_relu + folded batchnorm. Shapes fixed: x (256, 64, 512).
//
// Design (R15): R13's winning structure (4 cols/thread, part-resident,
// weights hoisted, single wave) at the measured FFMA2-pipe floor — so this
// round CUTS fma-pipe ops and fixes SM imbalance:
//  * leaky relu via sign-select multiplier (SHF+LOP3 on ALU pipe + 1 mul2)
//    -> saves 1 fma-op/pair AND is bit-exact x*0.01f
//  * BN scale folded into W2 at staging; shift folded into packed acc init
//    -> kills the epilogue FFMA
//  * grid 296 = 148 SMs x 2 CTAs: perfectly balanced single wave
//    (CTA = part-pair x 37 slices; 128-thread halves each own one part)

#define B_DIM 256
#define N_DIM 64
#define F_DIM 512
#define P_DIM 16
#define IN_DIM 4
#define H_DIM 16
#define O_DIM 3
#define COLS 4
#define SLICES 37
#define QUADS_PER_PART 32768           // B*F/4
#define THREADS_PER_PART (SLICES*128)  // 4736

typedef unsigned long long u64;
typedef unsigned int u32;

__device__ __forceinline__ u64 f2fma(u64 a, u64 b, u64 c) {
    u64 d;
    asm("fma.rn.f32x2 %0, %1, %2, %3;" : "=l"(d) : "l"(a), "l"(b), "l"(c));
    return d;
}
__device__ __forceinline__ u64 f2mul(u64 a, u64 b) {
    u64 d;
    asm("mul.rn.f32x2 %0, %1, %2;" : "=l"(d) : "l"(a), "l"(b));
    return d;
}
__device__ __forceinline__ u64 packf2(float lo, float hi) {
    u64 r;
    asm("mov.b64 %0, {%1, %2};" : "=l"(r) : "f"(lo), "f"(hi));
    return r;
}
__device__ __forceinline__ void unpackf2(u64 v, float& lo, float& hi) {
    asm("mov.b64 {%0, %1}, %2;" : "=f"(lo), "=f"(hi) : "l"(v));
}

// leaky(x) per packed lane: mult = sign ? 0.01f : 1.0f  (ALU: SHF+LOP3),
// then one packed mul (fma pipe). 0x3F800000^0x3C23D70A = 0x03A3D70A.
__device__ __forceinline__ u64 leaky2(u64 v) {
    u32 lo = (u32)v, hi = (u32)(v >> 32);
    u32 ml_mask = (u32)((int)lo >> 31);
    u32 mh_mask = (u32)((int)hi >> 31);
    u32 ml = 0x3F800000u ^ (ml_mask & 0x03A3D70Au);
    u32 mh = 0x3F800000u ^ (mh_mask & 0x03A3D70Au);
    u64 m = ((u64)mh << 32) | (u64)ml;
    return f2mul(v, m);
}

__global__ __launch_bounds__(256, 2)
void aggregate_joint_kernel(
    const float* __restrict__ x, const int* __restrict__ parts,
    const float* __restrict__ W1, const float* __restrict__ b1,
    const float* __restrict__ W2, const float* __restrict__ b2,
    const float* __restrict__ gamma, const float* __restrict__ beta,
    const float* __restrict__ mean, const float* __restrict__ var,
    float* __restrict__ out)
{
    // two parts per CTA (one per 128-thread half)
    __shared__ __align__(16) float sW1[2][IN_DIM * H_DIM];   // [lp][i*16+h]
    __shared__ __align__(16) float sW2T[2][O_DIM * H_DIM];   // scaled by sc
    __shared__ __align__(16) float sB1[2][H_DIM];
    __shared__ float sSh[2][O_DIM];                          // folded shift
    __shared__ int   sNi[2][IN_DIM];

    const int tid = threadIdx.x;
    const int lp  = tid >> 7;               // local part 0/1
    const int t   = tid & 127;
    const int pairIdx = blockIdx.x & 7;     // 8 part-pairs
    const int slice   = blockIdx.x >> 3;    // 0..36
    const int p = pairIdx * 2 + lp;         // global part of this half

    // ---- stage this half's part: weights (BN scale folded into W2) ----
    if (t < 64) {
        sW1[lp][t] = W1[p * (IN_DIM * H_DIM) + t];
    } else if (t < 112) {
        int idx = t - 64;                   // 0..47
        int o = idx >> 4;
        int hh = idx & 15;
        int g = p * O_DIM + o;
        float sc = gamma[g] * rsqrtf(var[g] + 1e-5f);
        sW2T[lp][idx] = W2[(p * H_DIM + hh) * O_DIM + o] * sc;
    } else {
        sB1[lp][t - 112] = b1[p * H_DIM + (t - 112)];
    }
    if (t < O_DIM) {
        int g = p * O_DIM + t;
        float sc = gamma[g] * rsqrtf(var[g] + 1e-5f);
        sSh[lp][t] = (b2[g] - mean[g]) * sc + beta[g];
    }
    if (t < IN_DIM) sNi[lp][t] = parts[p * IN_DIM + t];
    __syncthreads();

    // warp-uniform hoisted constants
    const int n0 = sNi[lp][0] * F_DIM;
    const int n1 = sNi[lp][1] * F_DIM;
    const int n2 = sNi[lp][2] * F_DIM;
    const int n3 = sNi[lp][3] * F_DIM;
    const int obase = p * (O_DIM * F_DIM);
    // packed acc inits carrying the folded shift: {sh, 0}
    const u64 sh0 = packf2(sSh[lp][0], 0.0f);
    const u64 sh1 = packf2(sSh[lp][1], 0.0f);
    const u64 sh2 = packf2(sSh[lp][2], 0.0f);

#pragma unroll 1
    for (int u = slice * 128 + t; u < QUADS_PER_PART; u += THREADS_PER_PART) {
        const int b = u >> 7;               // (u*4) / 512
        const int f = (u << 2) & 511;
        const float* xp = x + b * (N_DIM * F_DIM) + f;
        float* op = out + b * (P_DIM * O_DIM * F_DIM) + obase + f;

        // front-batched independent loads (MLP=4)
        float4 xc0 = *(const float4*)(xp + n0);
        float4 xc1 = *(const float4*)(xp + n1);
        float4 xc2 = *(const float4*)(xp + n2);
        float4 xc3 = *(const float4*)(xp + n3);

        // h pairs init from b1 (shared by 4 columns)
        const ulonglong2* bb = (const ulonglong2*)sB1[lp];
        ulonglong2 t0 = bb[0], t1 = bb[1], t2 = bb[2], t3 = bb[3];
        u64 h[COLS][8];
#pragma unroll
        for (int c = 0; c < COLS; c++) {
            h[c][0] = t0.x; h[c][1] = t0.y; h[c][2] = t1.x; h[c][3] = t1.y;
            h[c][4] = t2.x; h[c][5] = t2.y; h[c][6] = t3.x; h[c][7] = t3.y;
        }

        // layer 1
#pragma unroll
        for (int i = 0; i < IN_DIM; i++) {
            const ulonglong2* wr = (const ulonglong2*)&sW1[lp][i * H_DIM];
            ulonglong2 w0 = wr[0], w1 = wr[1], w2r = wr[2], w3 = wr[3];
            const u64 w[8] = {w0.x, w0.y, w1.x, w1.y, w2r.x, w2r.y, w3.x, w3.y};
            float4 xi = (i == 0) ? xc0 : (i == 1) ? xc1 : (i == 2) ? xc2 : xc3;
            u64 s[COLS];
            s[0] = packf2(xi.x, xi.x);
            s[1] = packf2(xi.y, xi.y);
            s[2] = packf2(xi.z, xi.z);
            s[3] = packf2(xi.w, xi.w);
#pragma unroll
            for (int j = 0; j < 8; j++) {
#pragma unroll
                for (int c = 0; c < COLS; c++)
                    h[c][j] = f2fma(s[c], w[j], h[c][j]);
            }
        }

        // leaky relu: 1 fma-pipe op/pair (select on ALU pipe)
#pragma unroll
        for (int c = 0; c < COLS; c++)
#pragma unroll
            for (int j = 0; j < 8; j++)
                h[c][j] = leaky2(h[c][j]);

        // layer 2 (W2 pre-scaled; shift folded into acc init) + leaky + store
#pragma unroll
        for (int o = 0; o < O_DIM; o++) {
            const ulonglong2* wr = (const ulonglong2*)&sW2T[lp][o * H_DIM];
            ulonglong2 a0 = wr[0], a1 = wr[1], a2 = wr[2], a3 = wr[3];
            const u64 a[8] = {a0.x, a0.y, a1.x, a1.y, a2.x, a2.y, a3.x, a3.y};
            const u64 init = (o == 0) ? sh0 : (o == 1) ? sh1 : sh2;
            u64 acc[COLS];
#pragma unroll
            for (int c = 0; c < COLS; c++)
                acc[c] = f2fma(h[c][0], a[0], init);
#pragma unroll
            for (int j = 1; j < 8; j++) {
#pragma unroll
                for (int c = 0; c < COLS; c++)
                    acc[c] = f2fma(h[c][j], a[j], acc[c]);
            }
            float4 vv;
            float lo, hi, v;
            unpackf2(acc[0], lo, hi);
            v = lo + hi; vv.x = fmaxf(v, 0.01f * v);
            unpackf2(acc[1], lo, hi);
            v = lo + hi; vv.y = fmaxf(v, 0.01f * v);
            unpackf2(acc[2], lo, hi);
            v = lo + hi; vv.z = fmaxf(v, 0.01f * v);
            unpackf2(acc[3], lo, hi);
            v = lo + hi; vv.w = fmaxf(v, 0.01f * v);
            *(float4*)(op + o * F_DIM) = vv;
        }
    }
}

extern "C" void kernel_launch(void* const* d_in, const int* in_sizes, int n_in,
                              void* d_out, int out_size) {
    const float* x     = (const float*)d_in[0];
    const int*   parts = (const int*)d_in[1];
    const float* W1    = (const float*)d_in[2];
    const float* b1    = (const float*)d_in[3];
    const float* W2    = (const float*)d_in[4];
    const float* b2    = (const float*)d_in[5];
    const float* gamma = (const float*)d_in[6];
    const float* beta  = (const float*)d_in[7];
    const float* mean  = (const float*)d_in[8];
    const float* var   = (const float*)d_in[9];
    float* out = (float*)d_out;

    // 296 CTAs = 148 SMs x 2 — perfectly balanced single wave
    // (8 part-pairs x 37 slices; each 128-thread half owns one part)
    aggregate_joint_kernel<<<8 * SLICES, 256>>>(x, parts, W1, b1, W2, b2,
                                                gamma, beta, mean, var, out);
}

// round 17
// speedup vs baseline: 1.7700x; 1.7700x over previous
#include <cuda_runtime.h>

// AggregateJoint: per-row block-diagonal MLP 64 -> (16x16) -> (16x3)
// with leaky_relu + folded batchnorm. Shapes fixed: x (256, 64, 512).
//
// Design (R17 = R16 resubmit after infra failure): R13's winning skeleton
// (4 cols/thread, part-resident CTAs, 256 CTAs single wave, power-of-2
// addressing) + software-pipelined x prefetch (iter k issues iter k+1's
// 4x LDG.128 before the math) so the LDG window is hidden instead of
// exposed 8x per thread. Weights stay in smem and are re-LDS'd per
// iteration via volatile asm (frees registers for the prefetch buffer;
// ~120 regs, no spills). BN scale folded into staged W2; BN shift folded
// into the packed accumulator init; layer-1 bias folded into the i=0 FMA.
// leaky = 0.505x + 0.495|x| packed (3 instr).

#define B_DIM 256
#define N_DIM 64
#define F_DIM 512
#define P_DIM 16
#define IN_DIM 4
#define H_DIM 16
#define O_DIM 3
#define COLS 4
#define K_ITERS 8
#define XSTRIDE (32 * N_DIM * F_DIM)           // floats
#define OSTRIDE (32 * P_DIM * O_DIM * F_DIM)   // floats

typedef unsigned long long u64;
typedef unsigned int u32;

__device__ __forceinline__ u64 f2fma(u64 a, u64 b, u64 c) {
    u64 d;
    asm("fma.rn.f32x2 %0, %1, %2, %3;" : "=l"(d) : "l"(a), "l"(b), "l"(c));
    return d;
}
__device__ __forceinline__ u64 f2mul(u64 a, u64 b) {
    u64 d;
    asm("mul.rn.f32x2 %0, %1, %2;" : "=l"(d) : "l"(a), "l"(b));
    return d;
}
__device__ __forceinline__ u64 packf2(float lo, float hi) {
    u64 r;
    asm("mov.b64 %0, {%1, %2};" : "=l"(r) : "f"(lo), "f"(hi));
    return r;
}
__device__ __forceinline__ void unpackf2(u64 v, float& lo, float& hi) {
    asm("mov.b64 {%0, %1}, %2;" : "=f"(lo), "=f"(hi) : "l"(v));
}
// volatile 16B shared load: pins weights to in-loop LDS (no reg hoisting)
__device__ __forceinline__ void lds128(u32 addr, u64& a, u64& b) {
    asm volatile("ld.shared.v2.u64 {%0, %1}, [%2];"
                 : "=l"(a), "=l"(b) : "r"(addr));
}

__global__ __launch_bounds__(256, 2)
void aggregate_joint_kernel(
    const float* __restrict__ x, const int* __restrict__ parts,
    const float* __restrict__ W1, const float* __restrict__ b1,
    const float* __restrict__ W2, const float* __restrict__ b2,
    const float* __restrict__ gamma, const float* __restrict__ beta,
    const float* __restrict__ mean, const float* __restrict__ var,
    float* __restrict__ out)
{
    __shared__ __align__(16) float sW1[IN_DIM * H_DIM];   // [i][h]
    __shared__ __align__(16) float sW2T[O_DIM * H_DIM];   // [o][h], BN-scaled
    __shared__ __align__(16) float sB1[H_DIM];
    __shared__ float sSh[O_DIM];                          // folded BN shift
    __shared__ int   sNi[IN_DIM];

    const int tid = threadIdx.x;
    const int p   = blockIdx.x & 15;        // part
    const int cip = blockIdx.x >> 4;        // cta-in-part 0..15

    // ---- stage this part's weights (L2-hit), fold BN ----
    if (tid < 64) {
        sW1[tid] = W1[p * (IN_DIM * H_DIM) + tid];
    } else if (tid < 112) {
        int idx = tid - 64;                 // 0..47
        int o = idx >> 4;
        int hh = idx & 15;
        int g = p * O_DIM + o;
        float sc = gamma[g] * rsqrtf(var[g] + 1e-5f);
        sW2T[idx] = W2[(p * H_DIM + hh) * O_DIM + o] * sc;
    } else if (tid < 128) {
        sB1[tid - 112] = b1[p * H_DIM + (tid - 112)];
    } else if (tid < 128 + O_DIM) {
        int o = tid - 128;
        int g = p * O_DIM + o;
        float sc = gamma[g] * rsqrtf(var[g] + 1e-5f);
        sSh[o] = (b2[g] - mean[g]) * sc + beta[g];
    } else if (tid < 128 + O_DIM + IN_DIM) {
        int i = tid - (128 + O_DIM);
        sNi[i] = parts[p * IN_DIM + i];
    }
    __syncthreads();

    // shared-space base addresses for volatile LDS
    const u32 w1a = (u32)__cvta_generic_to_shared(sW1);
    const u32 w2a = (u32)__cvta_generic_to_shared(sW2T);
    const u32 b1a = (u32)__cvta_generic_to_shared(sB1);

    // warp-uniform hoists
    const int n0 = sNi[0] * F_DIM;
    const int n1 = sNi[1] * F_DIM;
    const int n2 = sNi[2] * F_DIM;
    const int n3 = sNi[3] * F_DIM;
    const u64 sh0 = packf2(sSh[0], 0.0f);
    const u64 sh1 = packf2(sSh[1], 0.0f);
    const u64 sh2 = packf2(sSh[2], 0.0f);

    // leaky(x) = 0.505*x + 0.495*|x|
    const u64 AP = packf2(0.505f, 0.505f);
    const u64 BP = packf2(0.495f, 0.495f);

    // ---- thread work: 8 iterations, constant f, b = b0 + 32k ----
    const int T    = cip * 256 + tid;       // 0..4095
    const int col0 = T << 2;
    const int b0   = col0 >> 9;             // 0..31
    const int f    = col0 & 511;
    const float* xbase = x + ((size_t)b0 << 15) + f;              // b0*64*512
    float* op = out + (size_t)b0 * 24576 + (size_t)p * 1536 + f;

    // prime the pipeline: iteration 0's loads
    float4 xc0 = *(const float4*)(xbase + n0);
    float4 xc1 = *(const float4*)(xbase + n1);
    float4 xc2 = *(const float4*)(xbase + n2);
    float4 xc3 = *(const float4*)(xbase + n3);
    const float* xnext = xbase;

#pragma unroll 1
    for (int k = 0; k < K_ITERS; k++) {
        // ---- prefetch iter k+1 (last iter re-reads current ptr: L1 hit)
        xnext = (k < K_ITERS - 1) ? (xnext + XSTRIDE) : xnext;
        float4 xn0 = *(const float4*)(xnext + n0);
        float4 xn1 = *(const float4*)(xnext + n1);
        float4 xn2 = *(const float4*)(xnext + n2);
        float4 xn3 = *(const float4*)(xnext + n3);

        u64 h[COLS][8];
        // ---- layer 1, i=0: init from bias via FMA (no separate h init)
        {
            u64 bb[8];
            lds128(b1a +  0, bb[0], bb[1]);
            lds128(b1a + 16, bb[2], bb[3]);
            lds128(b1a + 32, bb[4], bb[5]);
            lds128(b1a + 48, bb[6], bb[7]);
            u64 w[8];
            lds128(w1a +  0, w[0], w[1]);
            lds128(w1a + 16, w[2], w[3]);
            lds128(w1a + 32, w[4], w[5]);
            lds128(w1a + 48, w[6], w[7]);
            u64 s[COLS];
            s[0] = packf2(xc0.x, xc0.x);
            s[1] = packf2(xc0.y, xc0.y);
            s[2] = packf2(xc0.z, xc0.z);
            s[3] = packf2(xc0.w, xc0.w);
#pragma unroll
            for (int j = 0; j < 8; j++)
#pragma unroll
                for (int c = 0; c < COLS; c++)
                    h[c][j] = f2fma(s[c], w[j], bb[j]);
        }
        // ---- layer 1, i=1..3
#pragma unroll
        for (int i = 1; i < IN_DIM; i++) {
            u64 w[8];
            lds128(w1a + i * 64 +  0, w[0], w[1]);
            lds128(w1a + i * 64 + 16, w[2], w[3]);
            lds128(w1a + i * 64 + 32, w[4], w[5]);
            lds128(w1a + i * 64 + 48, w[6], w[7]);
            float4 xi = (i == 1) ? xc1 : (i == 2) ? xc2 : xc3;
            u64 s[COLS];
            s[0] = packf2(xi.x, xi.x);
            s[1] = packf2(xi.y, xi.y);
            s[2] = packf2(xi.z, xi.z);
            s[3] = packf2(xi.w, xi.w);
#pragma unroll
            for (int j = 0; j < 8; j++)
#pragma unroll
                for (int c = 0; c < COLS; c++)
                    h[c][j] = f2fma(s[c], w[j], h[c][j]);
        }

        // ---- packed leaky relu (3 instr/pair: LOP3 + mul2 + fma2)
#pragma unroll
        for (int c = 0; c < COLS; c++)
#pragma unroll
            for (int j = 0; j < 8; j++) {
                u64 ab = h[c][j] & 0x7FFFFFFF7FFFFFFFULL;
                h[c][j] = f2fma(ab, BP, f2mul(h[c][j], AP));
            }

        // ---- layer 2 (W2 BN-scaled; shift folded into init) + leaky + store
#pragma unroll
        for (int o = 0; o < O_DIM; o++) {
            u64 a[8];
            lds128(w2a + o * 64 +  0, a[0], a[1]);
            lds128(w2a + o * 64 + 16, a[2], a[3]);
            lds128(w2a + o * 64 + 32, a[4], a[5]);
            lds128(w2a + o * 64 + 48, a[6], a[7]);
            const u64 init = (o == 0) ? sh0 : (o == 1) ? sh1 : sh2;
            u64 acc[COLS];
#pragma unroll
            for (int c = 0; c < COLS; c++)
                acc[c] = f2fma(h[c][0], a[0], init);
#pragma unroll
            for (int j = 1; j < 8; j++)
#pragma unroll
                for (int c = 0; c < COLS; c++)
                    acc[c] = f2fma(h[c][j], a[j], acc[c]);

            float4 vv;
            float lo, hi, v;
            unpackf2(acc[0], lo, hi);
            v = lo + hi; vv.x = fmaxf(v, 0.01f * v);
            unpackf2(acc[1], lo, hi);
            v = lo + hi; vv.y = fmaxf(v, 0.01f * v);
            unpackf2(acc[2], lo, hi);
            v = lo + hi; vv.z = fmaxf(v, 0.01f * v);
            unpackf2(acc[3], lo, hi);
            v = lo + hi; vv.w = fmaxf(v, 0.01f * v);
            *(float4*)(op + o * F_DIM) = vv;
        }
        op += OSTRIDE;

        // rotate prefetch buffers
        xc0 = xn0; xc1 = xn1; xc2 = xn2; xc3 = xn3;
    }
}

extern "C" void kernel_launch(void* const* d_in, const int* in_sizes, int n_in,
                              void* d_out, int out_size) {
    const float* x     = (const float*)d_in[0];
    const int*   parts = (const int*)d_in[1];
    const float* W1    = (const float*)d_in[2];
    const float* b1    = (const float*)d_in[3];
    const float* W2    = (const float*)d_in[4];
    const float* b2    = (const float*)d_in[5];
    const float* gamma = (const float*)d_in[6];
    const float* beta  = (const float*)d_in[7];
    const float* mean  = (const float*)d_in[8];
    const float* var   = (const float*)d_in[9];
    float* out = (float*)d_out;

    // 256 CTAs (16 parts x 16 CTAs/part) x 256 threads — single wave
    aggregate_joint_kernel<<<256, 256>>>(x, parts, W1, b1, W2, b2,
                                         gamma, beta, mean, var, out);
}